// round 1
// baseline (speedup 1.0000x reference)
#include <cuda_runtime.h>
#include <math.h>

// Problem constants
#define NB   8
#define NTOK 2048
#define DH   128
#define BQ   64     // query rows per attention block
#define BK   64     // keys per tile
#define KPAD 132    // padded row stride for Ks (bank-conflict mitigation)
#define PPAD 68     // padded row stride for P tile

// Scratch (device globals — no allocation allowed)
__device__ float g_q[NB * NTOK * DH];
__device__ float g_k[NB * NTOK * DH];
__device__ float g_v[NB * NTOK * DH];
__device__ float g_c[NB * NTOK * DH];

#define GEMM_SMEM ((64 * KPAD + 128 * 128) * 4)
#define ATTN_SMEM ((BQ * DH + BK * KPAD + BK * DH + BQ * PPAD + BQ + BK + BK) * 4)

// ---------------------------------------------------------------------------
// Y[M,128] = X[M,128] @ W[128,128]
// Block: 64 rows x full 128 cols. 256 threads, each owns a 4x8 micro-tile.
// ---------------------------------------------------------------------------
__global__ __launch_bounds__(256) void gemm128_kernel(
    const float* __restrict__ X, const float* __restrict__ W,
    float* __restrict__ Y) {
  extern __shared__ float sm[];
  float* As = sm;              // 64 x KPAD
  float* Bs = sm + 64 * KPAD;  // 128 x 128

  const int m0  = blockIdx.x * 64;
  const int tid = threadIdx.x;

  // Load A tile (64x128 floats = 2048 float4)
#pragma unroll
  for (int t = 0; t < 8; t++) {
    int i  = tid + t * 256;
    int r  = i >> 5;
    int c4 = i & 31;
    *reinterpret_cast<float4*>(&As[r * KPAD + c4 * 4]) =
        reinterpret_cast<const float4*>(X)[(m0 + r) * 32 + c4];
  }
  // Load full W (128x128 floats = 4096 float4)
#pragma unroll
  for (int t = 0; t < 16; t++) {
    int i = tid + t * 256;
    reinterpret_cast<float4*>(Bs)[i] = reinterpret_cast<const float4*>(W)[i];
  }
  __syncthreads();

  const int ty = tid >> 4, tx = tid & 15;
  const int r0 = ty * 4, c0 = tx * 8;

  float acc[4][8];
#pragma unroll
  for (int i = 0; i < 4; i++)
#pragma unroll
    for (int j = 0; j < 8; j++) acc[i][j] = 0.f;

  for (int kk = 0; kk < DH; kk += 4) {
    float areg[4][4];
#pragma unroll
    for (int i = 0; i < 4; i++) {
      float4 av = *reinterpret_cast<const float4*>(&As[(r0 + i) * KPAD + kk]);
      areg[i][0] = av.x; areg[i][1] = av.y; areg[i][2] = av.z; areg[i][3] = av.w;
    }
#pragma unroll
    for (int u = 0; u < 4; u++) {
      float4 b0 = *reinterpret_cast<const float4*>(&Bs[(kk + u) * DH + c0]);
      float4 b1 = *reinterpret_cast<const float4*>(&Bs[(kk + u) * DH + c0 + 4]);
#pragma unroll
      for (int i = 0; i < 4; i++) {
        float a = areg[i][u];
        acc[i][0] += a * b0.x; acc[i][1] += a * b0.y;
        acc[i][2] += a * b0.z; acc[i][3] += a * b0.w;
        acc[i][4] += a * b1.x; acc[i][5] += a * b1.y;
        acc[i][6] += a * b1.z; acc[i][7] += a * b1.w;
      }
    }
  }

#pragma unroll
  for (int i = 0; i < 4; i++) {
    float4 w0 = make_float4(acc[i][0], acc[i][1], acc[i][2], acc[i][3]);
    float4 w1 = make_float4(acc[i][4], acc[i][5], acc[i][6], acc[i][7]);
    *reinterpret_cast<float4*>(&Y[(m0 + r0 + i) * DH + c0])     = w0;
    *reinterpret_cast<float4*>(&Y[(m0 + r0 + i) * DH + c0 + 4]) = w1;
  }
}

// ---------------------------------------------------------------------------
// Fused flash attention with multiplicative distance decay + additive mask.
// Grid: (NTOK/BQ, NB). Block: 256 threads.
// Thread (ty,tx): S rows r0=4ty..+3, S cols {tx+16j}; O rows r0, cols tx*8..+7.
// Online softmax state (m,l) replicated in registers across each 16-lane group.
// ---------------------------------------------------------------------------
__global__ __launch_bounds__(256) void attn_kernel(
    const float* __restrict__ Q, const float* __restrict__ K,
    const float* __restrict__ V, const float* __restrict__ allele,
    const float* __restrict__ mask, float* __restrict__ Ctx) {
  extern __shared__ float sm[];
  float* Qs  = sm;                 // BQ x DH
  float* Ks  = Qs + BQ * DH;       // BK x KPAD
  float* Vs  = Ks + BK * KPAD;     // BK x DH
  float* Ps  = Vs + BK * DH;       // BQ x PPAD
  float* aqs = Ps + BQ * PPAD;     // BQ
  float* aks = aqs + BQ;           // BK
  float* mks = aks + BK;           // BK

  const int b   = blockIdx.y;
  const int q0  = blockIdx.x * BQ;
  const int tid = threadIdx.x;
  const int ty  = tid >> 4, tx = tid & 15;
  const int r0  = ty * 4;
  const float scale = 0.088388347648318447f;  // 1/sqrt(128)

  const float* Qg = Q + (size_t)(b * NTOK + q0) * DH;
#pragma unroll
  for (int t = 0; t < 8; t++) {
    int i = tid + t * 256;
    int r = i >> 5, c4 = i & 31;
    *reinterpret_cast<float4*>(&Qs[r * DH + c4 * 4]) =
        reinterpret_cast<const float4*>(Qg)[r * 32 + c4];
  }
  if (tid < BQ) aqs[tid] = allele[b * NTOK + q0 + tid];

  float m_run[4], l_run[4], o[4][8];
#pragma unroll
  for (int i = 0; i < 4; i++) {
    m_run[i] = -1e30f;
    l_run[i] = 0.f;
#pragma unroll
    for (int j = 0; j < 8; j++) o[i][j] = 0.f;
  }

  for (int kt = 0; kt < NTOK / BK; kt++) {
    __syncthreads();  // prev-tile PV done (and Qs/aqs ready on first iter)

    const float* Kg = K + (size_t)(b * NTOK + kt * BK) * DH;
    const float* Vg = V + (size_t)(b * NTOK + kt * BK) * DH;
#pragma unroll
    for (int t = 0; t < 8; t++) {
      int i = tid + t * 256;
      int r = i >> 5, c4 = i & 31;
      *reinterpret_cast<float4*>(&Ks[r * KPAD + c4 * 4]) =
          reinterpret_cast<const float4*>(Kg)[r * 32 + c4];
      *reinterpret_cast<float4*>(&Vs[r * DH + c4 * 4]) =
          reinterpret_cast<const float4*>(Vg)[r * 32 + c4];
    }
    if (tid < BK) {
      aks[tid] = allele[b * NTOK + kt * BK + tid];
      mks[tid] = mask[b * NTOK + kt * BK + tid];
    }
    __syncthreads();

    // ---- S = Q K^T (4x4 micro-tile) ----
    float s[4][4];
#pragma unroll
    for (int i = 0; i < 4; i++)
#pragma unroll
      for (int j = 0; j < 4; j++) s[i][j] = 0.f;

    for (int kk = 0; kk < DH; kk += 4) {
      float4 qv[4], kv[4];
#pragma unroll
      for (int i = 0; i < 4; i++)
        qv[i] = *reinterpret_cast<const float4*>(&Qs[(r0 + i) * DH + kk]);
#pragma unroll
      for (int j = 0; j < 4; j++)
        kv[j] = *reinterpret_cast<const float4*>(&Ks[(tx + 16 * j) * KPAD + kk]);
#pragma unroll
      for (int i = 0; i < 4; i++)
#pragma unroll
        for (int j = 0; j < 4; j++) {
          s[i][j] += qv[i].x * kv[j].x + qv[i].y * kv[j].y +
                     qv[i].z * kv[j].z + qv[i].w * kv[j].w;
        }
    }

    // ---- logits: scale * decay + mask; row max ----
    float rmax[4];
#pragma unroll
    for (int i = 0; i < 4; i++) {
      float aq = aqs[r0 + i];
      rmax[i] = -1e30f;
#pragma unroll
      for (int j = 0; j < 4; j++) {
        int c = tx + 16 * j;
        float dec = __expf(-0.1f * fabsf(aq - aks[c]));
        float lg  = s[i][j] * scale * dec + (1.0f - mks[c]) * (-1e9f);
        s[i][j]   = lg;
        rmax[i]   = fmaxf(rmax[i], lg);
      }
    }
#pragma unroll
    for (int i = 0; i < 4; i++) {
      rmax[i] = fmaxf(rmax[i], __shfl_xor_sync(0xffffffffu, rmax[i], 8));
      rmax[i] = fmaxf(rmax[i], __shfl_xor_sync(0xffffffffu, rmax[i], 4));
      rmax[i] = fmaxf(rmax[i], __shfl_xor_sync(0xffffffffu, rmax[i], 2));
      rmax[i] = fmaxf(rmax[i], __shfl_xor_sync(0xffffffffu, rmax[i], 1));
    }

    // ---- online softmax update (all 16 lanes compute identical state) ----
    float csc[4];
#pragma unroll
    for (int i = 0; i < 4; i++) {
      float mnew = fmaxf(m_run[i], rmax[i]);
      float sum  = 0.f;
#pragma unroll
      for (int j = 0; j < 4; j++) {
        float p = __expf(s[i][j] - mnew);
        s[i][j] = p;
        sum += p;
      }
      sum += __shfl_xor_sync(0xffffffffu, sum, 8);
      sum += __shfl_xor_sync(0xffffffffu, sum, 4);
      sum += __shfl_xor_sync(0xffffffffu, sum, 2);
      sum += __shfl_xor_sync(0xffffffffu, sum, 1);
      csc[i]   = __expf(m_run[i] - mnew);
      l_run[i] = l_run[i] * csc[i] + sum;
      m_run[i] = mnew;
    }

    // ---- write P tile (only own-warp rows; warp sync suffices) ----
#pragma unroll
    for (int i = 0; i < 4; i++)
#pragma unroll
      for (int j = 0; j < 4; j++)
        Ps[(r0 + i) * PPAD + tx + 16 * j] = s[i][j];
    __syncwarp();

    // ---- O = O*c + P @ V ----
    const int ocol = tx * 8;
#pragma unroll
    for (int i = 0; i < 4; i++) {
      float c = csc[i];
#pragma unroll
      for (int j = 0; j < 8; j++) o[i][j] *= c;
    }
#pragma unroll 2
    for (int kk = 0; kk < BK; kk++) {
      float4 v0 = *reinterpret_cast<const float4*>(&Vs[kk * DH + ocol]);
      float4 v1 = *reinterpret_cast<const float4*>(&Vs[kk * DH + ocol + 4]);
      float p0 = Ps[(r0 + 0) * PPAD + kk];
      float p1 = Ps[(r0 + 1) * PPAD + kk];
      float p2 = Ps[(r0 + 2) * PPAD + kk];
      float p3 = Ps[(r0 + 3) * PPAD + kk];
      o[0][0] += p0 * v0.x; o[0][1] += p0 * v0.y; o[0][2] += p0 * v0.z; o[0][3] += p0 * v0.w;
      o[0][4] += p0 * v1.x; o[0][5] += p0 * v1.y; o[0][6] += p0 * v1.z; o[0][7] += p0 * v1.w;
      o[1][0] += p1 * v0.x; o[1][1] += p1 * v0.y; o[1][2] += p1 * v0.z; o[1][3] += p1 * v0.w;
      o[1][4] += p1 * v1.x; o[1][5] += p1 * v1.y; o[1][6] += p1 * v1.z; o[1][7] += p1 * v1.w;
      o[2][0] += p2 * v0.x; o[2][1] += p2 * v0.y; o[2][2] += p2 * v0.z; o[2][3] += p2 * v0.w;
      o[2][4] += p2 * v1.x; o[2][5] += p2 * v1.y; o[2][6] += p2 * v1.z; o[2][7] += p2 * v1.w;
      o[3][0] += p3 * v0.x; o[3][1] += p3 * v0.y; o[3][2] += p3 * v0.z; o[3][3] += p3 * v0.w;
      o[3][4] += p3 * v1.x; o[3][5] += p3 * v1.y; o[3][6] += p3 * v1.z; o[3][7] += p3 * v1.w;
    }
  }

  // ---- epilogue: normalize and write ctx ----
  float* Og = Ctx + (size_t)(b * NTOK + q0) * DH;
  const int ocol = tx * 8;
#pragma unroll
  for (int i = 0; i < 4; i++) {
    float inv = 1.0f / l_run[i];
    float4 w0 = make_float4(o[i][0] * inv, o[i][1] * inv, o[i][2] * inv, o[i][3] * inv);
    float4 w1 = make_float4(o[i][4] * inv, o[i][5] * inv, o[i][6] * inv, o[i][7] * inv);
    *reinterpret_cast<float4*>(&Og[(r0 + i) * DH + ocol])     = w0;
    *reinterpret_cast<float4*>(&Og[(r0 + i) * DH + ocol + 4]) = w1;
  }
}

// ---------------------------------------------------------------------------
extern "C" void kernel_launch(void* const* d_in, const int* in_sizes, int n_in,
                              void* d_out, int out_size) {
  const float* X  = (const float*)d_in[0];
  const float* al = (const float*)d_in[1];
  const float* mk = (const float*)d_in[2];
  const float* Wq = (const float*)d_in[3];
  const float* Wk = (const float*)d_in[4];
  const float* Wv = (const float*)d_in[5];
  const float* Wo = (const float*)d_in[6];
  float* out = (float*)d_out;

  float *dq, *dk, *dv, *dc;
  cudaGetSymbolAddress((void**)&dq, g_q);
  cudaGetSymbolAddress((void**)&dk, g_k);
  cudaGetSymbolAddress((void**)&dv, g_v);
  cudaGetSymbolAddress((void**)&dc, g_c);

  cudaFuncSetAttribute(gemm128_kernel,
                       cudaFuncAttributeMaxDynamicSharedMemorySize, GEMM_SMEM);
  cudaFuncSetAttribute(attn_kernel,
                       cudaFuncAttributeMaxDynamicSharedMemorySize, ATTN_SMEM);

  const int M = NB * NTOK;
  dim3 gg(M / 64);
  gemm128_kernel<<<gg, 256, GEMM_SMEM>>>(X, Wq, dq);
  gemm128_kernel<<<gg, 256, GEMM_SMEM>>>(X, Wk, dk);
  gemm128_kernel<<<gg, 256, GEMM_SMEM>>>(X, Wv, dv);

  dim3 ga(NTOK / BQ, NB);
  attn_kernel<<<ga, 256, ATTN_SMEM>>>(dq, dk, dv, al, mk, dc);

  gemm128_kernel<<<gg, 256, GEMM_SMEM>>>(dc, Wo, out);
}

// round 4
// speedup vs baseline: 3.6261x; 3.6261x over previous
#include <cuda_runtime.h>
#include <cuda_bf16.h>
#include <stdint.h>

#define NB   8
#define NTOK 2048
#define DH   128
#define BQ   128
#define BK   64
#define NKT  (NTOK / BK)   // 32
#define KPS  68            // K smem row stride (uint32): banks 4g+t
#define VPS  36            // V^T smem row stride (uint32)
#define PPS  36            // P smem row stride (uint32)
#define XSTR 68            // proj smem stride (uint32)

// ---- packed bf16 hi/lo scratch (pairs in uint32) ----
__device__ uint32_t g_qh[NB * NTOK * 64];
__device__ uint32_t g_ql[NB * NTOK * 64];
__device__ uint32_t g_kh[NB * NTOK * 64];
__device__ uint32_t g_kl[NB * NTOK * 64];
__device__ uint32_t g_vh[NB * DH * (NTOK / 2)];   // V transposed: [b][d][tokenpair]
__device__ uint32_t g_vl[NB * DH * (NTOK / 2)];
__device__ float    g_c [NB * NTOK * DH];

#define QKV_SMEM (4 * 128 * XSTR * 4)
#define ATTN_U32 (4 * 64 * KPS + 4 * 128 * VPS + 2 * 128 * PPS + 256 + 128)
#define ATTN_SMEM (ATTN_U32 * 4)

// m16n8k16 bf16 mma, D += A*B
#define MMA_BF16(d, a, b0, b1)                                                 \
  asm volatile(                                                                \
      "mma.sync.aligned.m16n8k16.row.col.f32.bf16.bf16.f32 "                   \
      "{%0,%1,%2,%3}, {%4,%5,%6,%7}, {%8,%9}, {%0,%1,%2,%3};"                  \
      : "+f"(d[0]), "+f"(d[1]), "+f"(d[2]), "+f"(d[3])                         \
      : "r"(a[0]), "r"(a[1]), "r"(a[2]), "r"(a[3]), "r"(b0), "r"(b1))

// pack two floats into bf16x2: e -> low half, o -> high half
__device__ __forceinline__ uint32_t bfpack(float e, float o) {
  uint32_t r;
  asm("cvt.rn.bf16x2.f32 %0, %1, %2;" : "=r"(r) : "f"(o), "f"(e));
  return r;
}
__device__ __forceinline__ float bflo(uint32_t p) { return __uint_as_float(p << 16); }
__device__ __forceinline__ float bfhi(uint32_t p) { return __uint_as_float(p & 0xffff0000u); }
// residual (lo) pair given hi pair
__device__ __forceinline__ uint32_t bfres(uint32_t h, float e, float o) {
  return bfpack(e - bflo(h), o - bfhi(h));
}

__device__ __forceinline__ void cp16(void* smem_dst, const void* gmem_src) {
  unsigned s = (unsigned)__cvta_generic_to_shared(smem_dst);
  asm volatile("cp.async.cg.shared.global [%0], [%1], 16;" ::"r"(s), "l"(gmem_src));
}

// ---------------------------------------------------------------------------
// Fused QKV projections (3x-bf16). Block = 128 tokens. 8 warps.
// Outputs: Q/K packed pairs-over-d [tok][64] hi/lo; V transposed packed
// pairs-over-tokens [b][d][1024] hi/lo. Q pre-scaled by 1/sqrt(128).
// ---------------------------------------------------------------------------
__global__ __launch_bounds__(256, 1) void qkv_kernel(
    const float* __restrict__ X, const float* __restrict__ Wq,
    const float* __restrict__ Wk, const float* __restrict__ Wv,
    uint32_t* __restrict__ Qh, uint32_t* __restrict__ Ql,
    uint32_t* __restrict__ Kh, uint32_t* __restrict__ Kl,
    uint32_t* __restrict__ Vh, uint32_t* __restrict__ Vl) {
  extern __shared__ uint32_t usm[];
  uint32_t* Xh = usm;                 // [128][XSTR]
  uint32_t* Xl = Xh + 128 * XSTR;
  uint32_t* Wh = Xl + 128 * XSTR;     // [128 n][XSTR] (transposed, kpairs)
  uint32_t* Wl = Wh + 128 * XSTR;

  const int m0  = blockIdx.x * 128;
  const int tid = threadIdx.x;
  const int w = tid >> 5, lane = tid & 31;
  const int g = lane >> 2, t = lane & 3;
  const int r0 = w * 16 + g, r1 = r0 + 8;

  // stage X split+packed
#pragma unroll
  for (int it = 0; it < 16; it++) {
    int i = tid + it * 256;
    int r = i >> 5, c4 = i & 31;
    float4 xv = reinterpret_cast<const float4*>(X)[(size_t)(m0 + r) * 32 + c4];
    uint32_t h0 = bfpack(xv.x, xv.y), h1 = bfpack(xv.z, xv.w);
    Xh[r * XSTR + 2 * c4]     = h0;
    Xh[r * XSTR + 2 * c4 + 1] = h1;
    Xl[r * XSTR + 2 * c4]     = bfres(h0, xv.x, xv.y);
    Xl[r * XSTR + 2 * c4 + 1] = bfres(h1, xv.z, xv.w);
  }
  __syncthreads();

  uint32_t xah[8][4], xal[8][4];
#pragma unroll
  for (int s = 0; s < 8; s++) {
    xah[s][0] = Xh[r0 * XSTR + 8 * s + t];
    xah[s][1] = Xh[r1 * XSTR + 8 * s + t];
    xah[s][2] = Xh[r0 * XSTR + 8 * s + t + 4];
    xah[s][3] = Xh[r1 * XSTR + 8 * s + t + 4];
    xal[s][0] = Xl[r0 * XSTR + 8 * s + t];
    xal[s][1] = Xl[r1 * XSTR + 8 * s + t];
    xal[s][2] = Xl[r0 * XSTR + 8 * s + t + 4];
    xal[s][3] = Xl[r1 * XSTR + 8 * s + t + 4];
  }

  for (int ph = 0; ph < 3; ph++) {
    const float* W = (ph == 0) ? Wq : (ph == 1 ? Wk : Wv);
    __syncthreads();  // prior phase done with Wh/Wl region
    // stage W transposed: Wp[n][kpair]
#pragma unroll
    for (int it = 0; it < 32; it++) {
      int i = tid + it * 256;        // 0..8191
      int n = i & 127, kp = i >> 7;  // kp 0..63
      float w0 = W[(2 * kp) * 128 + n];
      float w1 = W[(2 * kp + 1) * 128 + n];
      uint32_t h = bfpack(w0, w1);
      Wh[n * XSTR + kp] = h;
      Wl[n * XSTR + kp] = bfres(h, w0, w1);
    }
    __syncthreads();

    float acc[16][4];
#pragma unroll
    for (int j = 0; j < 16; j++)
#pragma unroll
      for (int q = 0; q < 4; q++) acc[j][q] = 0.f;

#pragma unroll
    for (int s = 0; s < 8; s++) {
#pragma unroll
      for (int j = 0; j < 16; j++) {
        uint32_t b0h = Wh[(8 * j + g) * XSTR + 8 * s + t];
        uint32_t b1h = Wh[(8 * j + g) * XSTR + 8 * s + t + 4];
        uint32_t b0l = Wl[(8 * j + g) * XSTR + 8 * s + t];
        uint32_t b1l = Wl[(8 * j + g) * XSTR + 8 * s + t + 4];
        MMA_BF16(acc[j], xah[s], b0h, b1h);
        MMA_BF16(acc[j], xah[s], b0l, b1l);
        MMA_BF16(acc[j], xal[s], b0h, b1h);
      }
    }

    if (ph < 2) {
      uint32_t* Oh = (ph == 0) ? Qh : Kh;
      uint32_t* Ol = (ph == 0) ? Ql : Kl;
      const float sc = (ph == 0) ? 0.088388347648318447f : 1.0f;
#pragma unroll
      for (int j = 0; j < 16; j++) {
        float a0 = acc[j][0] * sc, a1 = acc[j][1] * sc;
        float a2 = acc[j][2] * sc, a3 = acc[j][3] * sc;
        uint32_t h0 = bfpack(a0, a1), h1 = bfpack(a2, a3);
        Oh[(size_t)(m0 + r0) * 64 + 4 * j + t] = h0;
        Ol[(size_t)(m0 + r0) * 64 + 4 * j + t] = bfres(h0, a0, a1);
        Oh[(size_t)(m0 + r1) * 64 + 4 * j + t] = h1;
        Ol[(size_t)(m0 + r1) * 64 + 4 * j + t] = bfres(h1, a2, a3);
      }
    } else {
      // V: transpose via smem (reuse W region), pack pairs over tokens
      __syncthreads();
      uint16_t* Th = (uint16_t*)Wh;            // [128 d][132 tok]
      uint16_t* Tl = Th + 128 * 132;
#pragma unroll
      for (int j = 0; j < 16; j++) {
        int c0 = 8 * j + 2 * t, c1 = c0 + 1;
#pragma unroll
        for (int q = 0; q < 4; q++) {
          int c = (q & 1) ? c1 : c0;
          int r = (q & 2) ? r1 : r0;
          float x = acc[j][q];
          __nv_bfloat16 h = __float2bfloat16(x);
          Th[c * 132 + r] = __bfloat16_as_ushort(h);
          Tl[c * 132 + r] =
              __bfloat16_as_ushort(__float2bfloat16(x - __bfloat162float(h)));
        }
      }
      __syncthreads();
      const int bb = m0 >> 11;
      const int loc2 = (m0 & 2047) >> 1;
      const uint32_t* Th32 = (const uint32_t*)Th;
      const uint32_t* Tl32 = (const uint32_t*)Tl;
#pragma unroll
      for (int it = 0; it < 32; it++) {
        int i = tid + it * 256;      // 0..8191
        int d = i >> 6, m = i & 63;
        size_t go = (size_t)(bb * DH + d) * (NTOK / 2) + loc2 + m;
        Vh[go] = Th32[d * 66 + m];
        Vl[go] = Tl32[d * 66 + m];
      }
    }
  }
}

// ---------------------------------------------------------------------------
// Output projection: out[M,128] = ctx[M,128] @ Wo (3x-bf16, fp32 out)
// ---------------------------------------------------------------------------
__global__ __launch_bounds__(256, 1) void oproj_kernel(
    const float* __restrict__ X, const float* __restrict__ W,
    float* __restrict__ Y) {
  extern __shared__ uint32_t usm[];
  uint32_t* Xh = usm;
  uint32_t* Xl = Xh + 128 * XSTR;
  uint32_t* Wh = Xl + 128 * XSTR;
  uint32_t* Wl = Wh + 128 * XSTR;

  const int m0  = blockIdx.x * 128;
  const int tid = threadIdx.x;
  const int w = tid >> 5, lane = tid & 31;
  const int g = lane >> 2, t = lane & 3;
  const int r0 = w * 16 + g, r1 = r0 + 8;

#pragma unroll
  for (int it = 0; it < 16; it++) {
    int i = tid + it * 256;
    int r = i >> 5, c4 = i & 31;
    float4 xv = reinterpret_cast<const float4*>(X)[(size_t)(m0 + r) * 32 + c4];
    uint32_t h0 = bfpack(xv.x, xv.y), h1 = bfpack(xv.z, xv.w);
    Xh[r * XSTR + 2 * c4]     = h0;
    Xh[r * XSTR + 2 * c4 + 1] = h1;
    Xl[r * XSTR + 2 * c4]     = bfres(h0, xv.x, xv.y);
    Xl[r * XSTR + 2 * c4 + 1] = bfres(h1, xv.z, xv.w);
  }
#pragma unroll
  for (int it = 0; it < 32; it++) {
    int i = tid + it * 256;
    int n = i & 127, kp = i >> 7;
    float w0 = W[(2 * kp) * 128 + n];
    float w1 = W[(2 * kp + 1) * 128 + n];
    uint32_t h = bfpack(w0, w1);
    Wh[n * XSTR + kp] = h;
    Wl[n * XSTR + kp] = bfres(h, w0, w1);
  }
  __syncthreads();

  uint32_t xah[8][4], xal[8][4];
#pragma unroll
  for (int s = 0; s < 8; s++) {
    xah[s][0] = Xh[r0 * XSTR + 8 * s + t];
    xah[s][1] = Xh[r1 * XSTR + 8 * s + t];
    xah[s][2] = Xh[r0 * XSTR + 8 * s + t + 4];
    xah[s][3] = Xh[r1 * XSTR + 8 * s + t + 4];
    xal[s][0] = Xl[r0 * XSTR + 8 * s + t];
    xal[s][1] = Xl[r1 * XSTR + 8 * s + t];
    xal[s][2] = Xl[r0 * XSTR + 8 * s + t + 4];
    xal[s][3] = Xl[r1 * XSTR + 8 * s + t + 4];
  }

  float acc[16][4];
#pragma unroll
  for (int j = 0; j < 16; j++)
#pragma unroll
    for (int q = 0; q < 4; q++) acc[j][q] = 0.f;

#pragma unroll
  for (int s = 0; s < 8; s++) {
#pragma unroll
    for (int j = 0; j < 16; j++) {
      uint32_t b0h = Wh[(8 * j + g) * XSTR + 8 * s + t];
      uint32_t b1h = Wh[(8 * j + g) * XSTR + 8 * s + t + 4];
      uint32_t b0l = Wl[(8 * j + g) * XSTR + 8 * s + t];
      uint32_t b1l = Wl[(8 * j + g) * XSTR + 8 * s + t + 4];
      MMA_BF16(acc[j], xah[s], b0h, b1h);
      MMA_BF16(acc[j], xah[s], b0l, b1l);
      MMA_BF16(acc[j], xal[s], b0h, b1h);
    }
  }

#pragma unroll
  for (int j = 0; j < 16; j++) {
    *reinterpret_cast<float2*>(&Y[(size_t)(m0 + r0) * DH + 8 * j + 2 * t]) =
        make_float2(acc[j][0], acc[j][1]);
    *reinterpret_cast<float2*>(&Y[(size_t)(m0 + r1) * DH + 8 * j + 2 * t]) =
        make_float2(acc[j][2], acc[j][3]);
  }
}

// ---------------------------------------------------------------------------
// Fused flash attention, 3x-bf16 mma, distance decay + mask.
// Grid (16, 8), 256 threads (8 warps x m16 rows).
// ---------------------------------------------------------------------------
__global__ __launch_bounds__(256, 1) void attn_kernel(
    const uint32_t* __restrict__ QpH, const uint32_t* __restrict__ QpL,
    const uint32_t* __restrict__ KpH, const uint32_t* __restrict__ KpL,
    const uint32_t* __restrict__ VpH, const uint32_t* __restrict__ VpL,
    const float* __restrict__ allele, const float* __restrict__ mask,
    float* __restrict__ Ctx) {
  extern __shared__ uint32_t usm[];
  uint32_t* KH = usm;                      // [2][64*KPS]
  uint32_t* KL = KH + 2 * 64 * KPS;
  uint32_t* VH = KL + 2 * 64 * KPS;        // [2][128*VPS]
  uint32_t* VL = VH + 2 * 128 * VPS;
  uint32_t* PH = VL + 2 * 128 * VPS;       // [128*PPS]
  uint32_t* PL = PH + 128 * PPS;
  float2*   uk2 = (float2*)(PL + 128 * PPS);  // [2][64] (u, 1/u)
  float*    bks = (float*)(uk2 + 128);        // [2][64]

  const int b   = blockIdx.y;
  const int q0  = blockIdx.x * BQ;
  const int tid = threadIdx.x;
  const int w = tid >> 5, lane = tid & 31;
  const int g = lane >> 2, t = lane & 3;

  // ---- Q fragments direct from global (pre-scaled, packed hi/lo)
  const uint32_t* qhg = QpH + (size_t)(b * NTOK + q0 + w * 16) * 64;
  const uint32_t* qlg = QpL + (size_t)(b * NTOK + q0 + w * 16) * 64;
  uint32_t qah[8][4], qal[8][4];
#pragma unroll
  for (int s = 0; s < 8; s++) {
    qah[s][0] = qhg[g * 64 + 8 * s + t];
    qah[s][1] = qhg[(g + 8) * 64 + 8 * s + t];
    qah[s][2] = qhg[g * 64 + 8 * s + t + 4];
    qah[s][3] = qhg[(g + 8) * 64 + 8 * s + t + 4];
    qal[s][0] = qlg[g * 64 + 8 * s + t];
    qal[s][1] = qlg[(g + 8) * 64 + 8 * s + t];
    qal[s][2] = qlg[g * 64 + 8 * s + t + 4];
    qal[s][3] = qlg[(g + 8) * 64 + 8 * s + t + 4];
  }
  float aq0 = allele[b * NTOK + q0 + w * 16 + g];
  float aq1 = allele[b * NTOK + q0 + w * 16 + g + 8];
  float uq0 = __expf(0.1f * aq0), iq0 = 1.0f / uq0;
  float uq1 = __expf(0.1f * aq1), iq1 = 1.0f / uq1;

  // ---- prefetch tile 0
  {
    const uint32_t* kh = KpH + (size_t)(b * NTOK) * 64;
    const uint32_t* kl = KpL + (size_t)(b * NTOK) * 64;
#pragma unroll
    for (int it = 0; it < 4; it++) {
      int i = tid + it * 256;
      int r = i >> 4, c = i & 15;
      cp16(&KH[r * KPS + c * 4], kh + r * 64 + c * 4);
      cp16(&KL[r * KPS + c * 4], kl + r * 64 + c * 4);
    }
    const uint32_t* vh = VpH + (size_t)b * DH * (NTOK / 2);
    const uint32_t* vl = VpL + (size_t)b * DH * (NTOK / 2);
#pragma unroll
    for (int it = 0; it < 4; it++) {
      int i = tid + it * 256;
      int r = i >> 3, c = i & 7;
      cp16(&VH[r * VPS + c * 4], vh + (size_t)r * (NTOK / 2) + c * 4);
      cp16(&VL[r * VPS + c * 4], vl + (size_t)r * (NTOK / 2) + c * 4);
    }
    asm volatile("cp.async.commit_group;");
    if (tid < BK) {
      float a = allele[b * NTOK + tid];
      float u = __expf(0.1f * a);
      uk2[tid] = make_float2(u, 1.0f / u);
      bks[tid] = (1.0f - mask[b * NTOK + tid]) * -1e9f;
    }
  }

  float o[16][4];
#pragma unroll
  for (int j = 0; j < 16; j++)
#pragma unroll
    for (int q = 0; q < 4; q++) o[j][q] = 0.f;
  float m0 = -1e30f, m1 = -1e30f, l0 = 0.f, l1 = 0.f;

  for (int kt = 0; kt < NKT; kt++) {
    const int buf = kt & 1;
    asm volatile("cp.async.wait_group 0;");
    __syncthreads();

    if (kt + 1 < NKT) {
      const uint32_t* kh = KpH + (size_t)(b * NTOK + (kt + 1) * BK) * 64;
      const uint32_t* kl = KpL + (size_t)(b * NTOK + (kt + 1) * BK) * 64;
      uint32_t* dkh = KH + (buf ^ 1) * 64 * KPS;
      uint32_t* dkl = KL + (buf ^ 1) * 64 * KPS;
#pragma unroll
      for (int it = 0; it < 4; it++) {
        int i = tid + it * 256;
        int r = i >> 4, c = i & 15;
        cp16(&dkh[r * KPS + c * 4], kh + r * 64 + c * 4);
        cp16(&dkl[r * KPS + c * 4], kl + r * 64 + c * 4);
      }
      const uint32_t* vh = VpH + (size_t)b * DH * (NTOK / 2) + (kt + 1) * 32;
      const uint32_t* vl = VpL + (size_t)b * DH * (NTOK / 2) + (kt + 1) * 32;
      uint32_t* dvh = VH + (buf ^ 1) * 128 * VPS;
      uint32_t* dvl = VL + (buf ^ 1) * 128 * VPS;
#pragma unroll
      for (int it = 0; it < 4; it++) {
        int i = tid + it * 256;
        int r = i >> 3, c = i & 7;
        cp16(&dvh[r * VPS + c * 4], vh + (size_t)r * (NTOK / 2) + c * 4);
        cp16(&dvl[r * VPS + c * 4], vl + (size_t)r * (NTOK / 2) + c * 4);
      }
      asm volatile("cp.async.commit_group;");
      if (tid < BK) {
        float a = allele[b * NTOK + (kt + 1) * BK + tid];
        float u = __expf(0.1f * a);
        uk2[(buf ^ 1) * 64 + tid] = make_float2(u, 1.0f / u);
        bks[(buf ^ 1) * 64 + tid] =
            (1.0f - mask[b * NTOK + (kt + 1) * BK + tid]) * -1e9f;
      }
    }

    // ---- S = Q K^T (m16 x n64 x k128, 3-mma split)
    float sacc[8][4];
#pragma unroll
    for (int j = 0; j < 8; j++)
#pragma unroll
      for (int q = 0; q < 4; q++) sacc[j][q] = 0.f;

    const uint32_t* kbh = KH + buf * 64 * KPS;
    const uint32_t* kbl = KL + buf * 64 * KPS;
#pragma unroll
    for (int s = 0; s < 8; s++) {
#pragma unroll
      for (int j = 0; j < 8; j++) {
        uint32_t b0h = kbh[(8 * j + g) * KPS + 8 * s + t];
        uint32_t b1h = kbh[(8 * j + g) * KPS + 8 * s + t + 4];
        uint32_t b0l = kbl[(8 * j + g) * KPS + 8 * s + t];
        uint32_t b1l = kbl[(8 * j + g) * KPS + 8 * s + t + 4];
        MMA_BF16(sacc[j], qah[s], b0h, b1h);
        MMA_BF16(sacc[j], qah[s], b0l, b1l);
        MMA_BF16(sacc[j], qal[s], b0h, b1h);
      }
    }

    // ---- logits = S*decay + bias; row max
    const float2* ukb = &uk2[buf * 64];
    const float*  bb  = &bks[buf * 64];
    float rmax0 = -1e30f, rmax1 = -1e30f;
#pragma unroll
    for (int j = 0; j < 8; j++) {
      int c = 8 * j + 2 * t;
      float4 uu = *reinterpret_cast<const float4*>(&ukb[c]);
      float2 bias = *reinterpret_cast<const float2*>(&bb[c]);
      float d00 = fminf(uq0 * uu.y, iq0 * uu.x);
      float d01 = fminf(uq0 * uu.w, iq0 * uu.z);
      float d10 = fminf(uq1 * uu.y, iq1 * uu.x);
      float d11 = fminf(uq1 * uu.w, iq1 * uu.z);
      sacc[j][0] = sacc[j][0] * d00 + bias.x;
      sacc[j][1] = sacc[j][1] * d01 + bias.y;
      sacc[j][2] = sacc[j][2] * d10 + bias.x;
      sacc[j][3] = sacc[j][3] * d11 + bias.y;
      rmax0 = fmaxf(rmax0, fmaxf(sacc[j][0], sacc[j][1]));
      rmax1 = fmaxf(rmax1, fmaxf(sacc[j][2], sacc[j][3]));
    }
    rmax0 = fmaxf(rmax0, __shfl_xor_sync(0xffffffffu, rmax0, 1));
    rmax0 = fmaxf(rmax0, __shfl_xor_sync(0xffffffffu, rmax0, 2));
    rmax1 = fmaxf(rmax1, __shfl_xor_sync(0xffffffffu, rmax1, 1));
    rmax1 = fmaxf(rmax1, __shfl_xor_sync(0xffffffffu, rmax1, 2));

    float mn0 = fmaxf(m0, rmax0), mn1 = fmaxf(m1, rmax1);
    float sum0 = 0.f, sum1 = 0.f;
#pragma unroll
    for (int j = 0; j < 8; j++) {
      float p00 = __expf(sacc[j][0] - mn0);
      float p01 = __expf(sacc[j][1] - mn0);
      float p10 = __expf(sacc[j][2] - mn1);
      float p11 = __expf(sacc[j][3] - mn1);
      sum0 += p00 + p01;
      sum1 += p10 + p11;
      uint32_t h0 = bfpack(p00, p01);
      uint32_t h1 = bfpack(p10, p11);
      PH[(w * 16 + g) * PPS + 4 * j + t] = h0;
      PL[(w * 16 + g) * PPS + 4 * j + t] = bfres(h0, p00, p01);
      PH[(w * 16 + g + 8) * PPS + 4 * j + t] = h1;
      PL[(w * 16 + g + 8) * PPS + 4 * j + t] = bfres(h1, p10, p11);
    }
    sum0 += __shfl_xor_sync(0xffffffffu, sum0, 1);
    sum0 += __shfl_xor_sync(0xffffffffu, sum0, 2);
    sum1 += __shfl_xor_sync(0xffffffffu, sum1, 1);
    sum1 += __shfl_xor_sync(0xffffffffu, sum1, 2);

    float cs0 = __expf(m0 - mn0), cs1 = __expf(m1 - mn1);
    l0 = l0 * cs0 + sum0;
    l1 = l1 * cs1 + sum1;
    m0 = mn0; m1 = mn1;
#pragma unroll
    for (int j = 0; j < 16; j++) {
      o[j][0] *= cs0; o[j][1] *= cs0;
      o[j][2] *= cs1; o[j][3] *= cs1;
    }
    __syncwarp();  // P rows warp-private

    // ---- O += P V (m16 x n128 x k64, 3-mma split)
    const uint32_t* vbh = VH + buf * 128 * VPS;
    const uint32_t* vbl = VL + buf * 128 * VPS;
#pragma unroll
    for (int s2 = 0; s2 < 4; s2++) {
      uint32_t pah[4], pal[4];
      pah[0] = PH[(w * 16 + g) * PPS + 8 * s2 + t];
      pah[1] = PH[(w * 16 + g + 8) * PPS + 8 * s2 + t];
      pah[2] = PH[(w * 16 + g) * PPS + 8 * s2 + t + 4];
      pah[3] = PH[(w * 16 + g + 8) * PPS + 8 * s2 + t + 4];
      pal[0] = PL[(w * 16 + g) * PPS + 8 * s2 + t];
      pal[1] = PL[(w * 16 + g + 8) * PPS + 8 * s2 + t];
      pal[2] = PL[(w * 16 + g) * PPS + 8 * s2 + t + 4];
      pal[3] = PL[(w * 16 + g + 8) * PPS + 8 * s2 + t + 4];
#pragma unroll
      for (int j2 = 0; j2 < 16; j2++) {
        uint32_t b0h = vbh[(8 * j2 + g) * VPS + 8 * s2 + t];
        uint32_t b1h = vbh[(8 * j2 + g) * VPS + 8 * s2 + t + 4];
        uint32_t b0l = vbl[(8 * j2 + g) * VPS + 8 * s2 + t];
        uint32_t b1l = vbl[(8 * j2 + g) * VPS + 8 * s2 + t + 4];
        MMA_BF16(o[j2], pah, b0h, b1h);
        MMA_BF16(o[j2], pah, b0l, b1l);
        MMA_BF16(o[j2], pal, b0h, b1h);
      }
    }
  }

  // ---- epilogue
  float inv0 = 1.0f / l0, inv1 = 1.0f / l1;
  float* Og = Ctx + (size_t)(b * NTOK + q0) * DH;
#pragma unroll
  for (int j2 = 0; j2 < 16; j2++) {
    *reinterpret_cast<float2*>(&Og[(w * 16 + g) * DH + 8 * j2 + 2 * t]) =
        make_float2(o[j2][0] * inv0, o[j2][1] * inv0);
    *reinterpret_cast<float2*>(&Og[(w * 16 + g + 8) * DH + 8 * j2 + 2 * t]) =
        make_float2(o[j2][2] * inv1, o[j2][3] * inv1);
  }
}

// ---------------------------------------------------------------------------
extern "C" void kernel_launch(void* const* d_in, const int* in_sizes, int n_in,
                              void* d_out, int out_size) {
  const float* X  = (const float*)d_in[0];
  const float* al = (const float*)d_in[1];
  const float* mk = (const float*)d_in[2];
  const float* Wq = (const float*)d_in[3];
  const float* Wk = (const float*)d_in[4];
  const float* Wv = (const float*)d_in[5];
  const float* Wo = (const float*)d_in[6];
  float* out = (float*)d_out;

  uint32_t *qh, *ql, *kh, *kl, *vh, *vl;
  float* dc;
  cudaGetSymbolAddress((void**)&qh, g_qh);
  cudaGetSymbolAddress((void**)&ql, g_ql);
  cudaGetSymbolAddress((void**)&kh, g_kh);
  cudaGetSymbolAddress((void**)&kl, g_kl);
  cudaGetSymbolAddress((void**)&vh, g_vh);
  cudaGetSymbolAddress((void**)&vl, g_vl);
  cudaGetSymbolAddress((void**)&dc, g_c);

  cudaFuncSetAttribute(qkv_kernel,
                       cudaFuncAttributeMaxDynamicSharedMemorySize, QKV_SMEM);
  cudaFuncSetAttribute(oproj_kernel,
                       cudaFuncAttributeMaxDynamicSharedMemorySize, QKV_SMEM);
  cudaFuncSetAttribute(attn_kernel,
                       cudaFuncAttributeMaxDynamicSharedMemorySize, ATTN_SMEM);

  qkv_kernel<<<NB * NTOK / 128, 256, QKV_SMEM>>>(X, Wq, Wk, Wv, qh, ql, kh, kl,
                                                 vh, vl);
  attn_kernel<<<dim3(NTOK / BQ, NB), 256, ATTN_SMEM>>>(qh, ql, kh, kl, vh, vl,
                                                       al, mk, dc);
  oproj_kernel<<<NB * NTOK / 128, 256, QKV_SMEM>>>(dc, Wo, out);
}

// round 5
// speedup vs baseline: 3.9702x; 1.0949x over previous
#include <cuda_runtime.h>
#include <cuda_bf16.h>
#include <stdint.h>

#define NB   8
#define NTOK 2048
#define DH   128
#define BQ   128
#define BK   64
#define NKT  (NTOK / BK)   // 32
#define KPS  68            // K smem row stride (uint32)
#define VPS  36            // V^T smem row stride (uint32)
#define XSTR 68            // proj smem stride (uint32)

// ---- packed bf16 hi/lo scratch (pairs in uint32) ----
__device__ uint32_t g_qh[NB * NTOK * 64];
__device__ uint32_t g_ql[NB * NTOK * 64];
__device__ uint32_t g_kh[NB * NTOK * 64];
__device__ uint32_t g_kl[NB * NTOK * 64];
__device__ uint32_t g_vh[NB * DH * (NTOK / 2)];   // V transposed: [b][d][tokenpair]
__device__ uint32_t g_vl[NB * DH * (NTOK / 2)];
__device__ float    g_c [NB * NTOK * DH];

#define QKV_SMEM (4 * 128 * XSTR * 4)
#define ATTN_U32 (4 * 64 * KPS + 4 * 128 * VPS + 256 + 128)
#define ATTN_SMEM (ATTN_U32 * 4)

// m16n8k16 bf16 mma, D += A*B
#define MMA_BF16(d, a, b0, b1)                                                 \
  asm volatile(                                                                \
      "mma.sync.aligned.m16n8k16.row.col.f32.bf16.bf16.f32 "                   \
      "{%0,%1,%2,%3}, {%4,%5,%6,%7}, {%8,%9}, {%0,%1,%2,%3};"                  \
      : "+f"(d[0]), "+f"(d[1]), "+f"(d[2]), "+f"(d[3])                         \
      : "r"(a[0]), "r"(a[1]), "r"(a[2]), "r"(a[3]), "r"(b0), "r"(b1))

__device__ __forceinline__ void ldsm4(uint32_t& r0, uint32_t& r1, uint32_t& r2,
                                      uint32_t& r3, uint32_t saddr) {
  asm volatile(
      "ldmatrix.sync.aligned.m8n8.x4.shared.b16 {%0,%1,%2,%3}, [%4];"
      : "=r"(r0), "=r"(r1), "=r"(r2), "=r"(r3)
      : "r"(saddr));
}

// pack two floats into bf16x2: e -> low half, o -> high half
__device__ __forceinline__ uint32_t bfpack(float e, float o) {
  uint32_t r;
  asm("cvt.rn.bf16x2.f32 %0, %1, %2;" : "=r"(r) : "f"(o), "f"(e));
  return r;
}
__device__ __forceinline__ float bflo(uint32_t p) { return __uint_as_float(p << 16); }
__device__ __forceinline__ float bfhi(uint32_t p) { return __uint_as_float(p & 0xffff0000u); }
__device__ __forceinline__ uint32_t bfres(uint32_t h, float e, float o) {
  return bfpack(e - bflo(h), o - bfhi(h));
}

__device__ __forceinline__ void cp16(void* smem_dst, const void* gmem_src) {
  unsigned s = (unsigned)__cvta_generic_to_shared(smem_dst);
  asm volatile("cp.async.cg.shared.global [%0], [%1], 16;" ::"r"(s), "l"(gmem_src));
}

// ---------------------------------------------------------------------------
// Fused QKV projections (3x-bf16, ldmatrix B-loads).
// ---------------------------------------------------------------------------
__global__ __launch_bounds__(256, 1) void qkv_kernel(
    const float* __restrict__ X, const float* __restrict__ Wq,
    const float* __restrict__ Wk, const float* __restrict__ Wv,
    uint32_t* __restrict__ Qh, uint32_t* __restrict__ Ql,
    uint32_t* __restrict__ Kh, uint32_t* __restrict__ Kl,
    uint32_t* __restrict__ Vh, uint32_t* __restrict__ Vl) {
  extern __shared__ uint32_t usm[];
  uint32_t* Xh = usm;                 // [128][XSTR]
  uint32_t* Xl = Xh + 128 * XSTR;
  uint32_t* Wh = Xl + 128 * XSTR;     // [128 n][XSTR] (transposed, kpairs)
  uint32_t* Wl = Wh + 128 * XSTR;

  const int m0  = blockIdx.x * 128;
  const int tid = threadIdx.x;
  const int w = tid >> 5, lane = tid & 31;
  const int g = lane >> 2, t = lane & 3;
  const int r0 = w * 16 + g, r1 = r0 + 8;
  const int lm = lane >> 3, lr = lane & 7;
  const uint32_t smb = (uint32_t)__cvta_generic_to_shared(usm);
  const uint32_t whb = smb + (2 * 128 * XSTR) * 4;
  const uint32_t wlb = smb + (3 * 128 * XSTR) * 4;
  const uint32_t wcc = ((8 * (lm >> 1) + lr) * XSTR + 4 * (lm & 1)) * 4;

  // stage X split+packed
#pragma unroll
  for (int it = 0; it < 16; it++) {
    int i = tid + it * 256;
    int r = i >> 5, c4 = i & 31;
    float4 xv = reinterpret_cast<const float4*>(X)[(size_t)(m0 + r) * 32 + c4];
    uint32_t h0 = bfpack(xv.x, xv.y), h1 = bfpack(xv.z, xv.w);
    Xh[r * XSTR + 2 * c4]     = h0;
    Xh[r * XSTR + 2 * c4 + 1] = h1;
    Xl[r * XSTR + 2 * c4]     = bfres(h0, xv.x, xv.y);
    Xl[r * XSTR + 2 * c4 + 1] = bfres(h1, xv.z, xv.w);
  }
  __syncthreads();

  uint32_t xah[8][4], xal[8][4];
#pragma unroll
  for (int s = 0; s < 8; s++) {
    xah[s][0] = Xh[r0 * XSTR + 8 * s + t];
    xah[s][1] = Xh[r1 * XSTR + 8 * s + t];
    xah[s][2] = Xh[r0 * XSTR + 8 * s + t + 4];
    xah[s][3] = Xh[r1 * XSTR + 8 * s + t + 4];
    xal[s][0] = Xl[r0 * XSTR + 8 * s + t];
    xal[s][1] = Xl[r1 * XSTR + 8 * s + t];
    xal[s][2] = Xl[r0 * XSTR + 8 * s + t + 4];
    xal[s][3] = Xl[r1 * XSTR + 8 * s + t + 4];
  }

  for (int ph = 0; ph < 3; ph++) {
    const float* W = (ph == 0) ? Wq : (ph == 1 ? Wk : Wv);
    __syncthreads();  // prior phase done with Wh/Wl region
#pragma unroll
    for (int it = 0; it < 32; it++) {
      int i = tid + it * 256;        // 0..8191
      int n = i & 127, kp = i >> 7;  // kp 0..63
      float w0 = W[(2 * kp) * 128 + n];
      float w1 = W[(2 * kp + 1) * 128 + n];
      uint32_t h = bfpack(w0, w1);
      Wh[n * XSTR + kp] = h;
      Wl[n * XSTR + kp] = bfres(h, w0, w1);
    }
    __syncthreads();

    float acc[16][4];
#pragma unroll
    for (int j = 0; j < 16; j++)
#pragma unroll
      for (int q = 0; q < 4; q++) acc[j][q] = 0.f;

#pragma unroll
    for (int s = 0; s < 8; s++) {
#pragma unroll
      for (int jp = 0; jp < 8; jp++) {
        uint32_t h0, h1, h2, h3, l0, l1, l2, l3;
        ldsm4(h0, h1, h2, h3, whb + jp * (16 * XSTR * 4) + s * 32 + wcc);
        ldsm4(l0, l1, l2, l3, wlb + jp * (16 * XSTR * 4) + s * 32 + wcc);
        MMA_BF16(acc[2 * jp], xah[s], h0, h1);
        MMA_BF16(acc[2 * jp], xal[s], h0, h1);
        MMA_BF16(acc[2 * jp], xah[s], l0, l1);
        MMA_BF16(acc[2 * jp + 1], xah[s], h2, h3);
        MMA_BF16(acc[2 * jp + 1], xal[s], h2, h3);
        MMA_BF16(acc[2 * jp + 1], xah[s], l2, l3);
      }
    }

    if (ph < 2) {
      uint32_t* Oh = (ph == 0) ? Qh : Kh;
      uint32_t* Ol = (ph == 0) ? Ql : Kl;
      const float sc = (ph == 0) ? 0.088388347648318447f : 1.0f;
#pragma unroll
      for (int j = 0; j < 16; j++) {
        float a0 = acc[j][0] * sc, a1 = acc[j][1] * sc;
        float a2 = acc[j][2] * sc, a3 = acc[j][3] * sc;
        uint32_t h0 = bfpack(a0, a1), h1 = bfpack(a2, a3);
        Oh[(size_t)(m0 + r0) * 64 + 4 * j + t] = h0;
        Ol[(size_t)(m0 + r0) * 64 + 4 * j + t] = bfres(h0, a0, a1);
        Oh[(size_t)(m0 + r1) * 64 + 4 * j + t] = h1;
        Ol[(size_t)(m0 + r1) * 64 + 4 * j + t] = bfres(h1, a2, a3);
      }
    } else {
      // V: transpose via smem (reuse W region), pack pairs over tokens
      __syncthreads();
      uint16_t* Th = (uint16_t*)Wh;            // [128 d][132 tok]
      uint16_t* Tl = Th + 128 * 132;
#pragma unroll
      for (int j = 0; j < 16; j++) {
        int c0 = 8 * j + 2 * t, c1 = c0 + 1;
#pragma unroll
        for (int q = 0; q < 4; q++) {
          int c = (q & 1) ? c1 : c0;
          int r = (q & 2) ? r1 : r0;
          float x = acc[j][q];
          __nv_bfloat16 h = __float2bfloat16(x);
          Th[c * 132 + r] = __bfloat16_as_ushort(h);
          Tl[c * 132 + r] =
              __bfloat16_as_ushort(__float2bfloat16(x - __bfloat162float(h)));
        }
      }
      __syncthreads();
      const int bb = m0 >> 11;
      const int loc2 = (m0 & 2047) >> 1;
      const uint32_t* Th32 = (const uint32_t*)Th;
      const uint32_t* Tl32 = (const uint32_t*)Tl;
#pragma unroll
      for (int it = 0; it < 32; it++) {
        int i = tid + it * 256;      // 0..8191
        int d = i >> 6, m = i & 63;
        size_t go = (size_t)(bb * DH + d) * (NTOK / 2) + loc2 + m;
        Vh[go] = Th32[d * 66 + m];
        Vl[go] = Tl32[d * 66 + m];
      }
    }
  }
}

// ---------------------------------------------------------------------------
// Output projection: out[M,128] = ctx[M,128] @ Wo (3x-bf16, ldmatrix B-loads)
// ---------------------------------------------------------------------------
__global__ __launch_bounds__(256, 1) void oproj_kernel(
    const float* __restrict__ X, const float* __restrict__ W,
    float* __restrict__ Y) {
  extern __shared__ uint32_t usm[];
  uint32_t* Xh = usm;
  uint32_t* Xl = Xh + 128 * XSTR;
  uint32_t* Wh = Xl + 128 * XSTR;
  uint32_t* Wl = Wh + 128 * XSTR;

  const int m0  = blockIdx.x * 128;
  const int tid = threadIdx.x;
  const int w = tid >> 5, lane = tid & 31;
  const int g = lane >> 2, t = lane & 3;
  const int r0 = w * 16 + g, r1 = r0 + 8;
  const int lm = lane >> 3, lr = lane & 7;
  const uint32_t smb = (uint32_t)__cvta_generic_to_shared(usm);
  const uint32_t whb = smb + (2 * 128 * XSTR) * 4;
  const uint32_t wlb = smb + (3 * 128 * XSTR) * 4;
  const uint32_t wcc = ((8 * (lm >> 1) + lr) * XSTR + 4 * (lm & 1)) * 4;

#pragma unroll
  for (int it = 0; it < 16; it++) {
    int i = tid + it * 256;
    int r = i >> 5, c4 = i & 31;
    float4 xv = reinterpret_cast<const float4*>(X)[(size_t)(m0 + r) * 32 + c4];
    uint32_t h0 = bfpack(xv.x, xv.y), h1 = bfpack(xv.z, xv.w);
    Xh[r * XSTR + 2 * c4]     = h0;
    Xh[r * XSTR + 2 * c4 + 1] = h1;
    Xl[r * XSTR + 2 * c4]     = bfres(h0, xv.x, xv.y);
    Xl[r * XSTR + 2 * c4 + 1] = bfres(h1, xv.z, xv.w);
  }
#pragma unroll
  for (int it = 0; it < 32; it++) {
    int i = tid + it * 256;
    int n = i & 127, kp = i >> 7;
    float w0 = W[(2 * kp) * 128 + n];
    float w1 = W[(2 * kp + 1) * 128 + n];
    uint32_t h = bfpack(w0, w1);
    Wh[n * XSTR + kp] = h;
    Wl[n * XSTR + kp] = bfres(h, w0, w1);
  }
  __syncthreads();

  uint32_t xah[8][4], xal[8][4];
#pragma unroll
  for (int s = 0; s < 8; s++) {
    xah[s][0] = Xh[r0 * XSTR + 8 * s + t];
    xah[s][1] = Xh[r1 * XSTR + 8 * s + t];
    xah[s][2] = Xh[r0 * XSTR + 8 * s + t + 4];
    xah[s][3] = Xh[r1 * XSTR + 8 * s + t + 4];
    xal[s][0] = Xl[r0 * XSTR + 8 * s + t];
    xal[s][1] = Xl[r1 * XSTR + 8 * s + t];
    xal[s][2] = Xl[r0 * XSTR + 8 * s + t + 4];
    xal[s][3] = Xl[r1 * XSTR + 8 * s + t + 4];
  }

  float acc[16][4];
#pragma unroll
  for (int j = 0; j < 16; j++)
#pragma unroll
    for (int q = 0; q < 4; q++) acc[j][q] = 0.f;

#pragma unroll
  for (int s = 0; s < 8; s++) {
#pragma unroll
    for (int jp = 0; jp < 8; jp++) {
      uint32_t h0, h1, h2, h3, l0, l1, l2, l3;
      ldsm4(h0, h1, h2, h3, whb + jp * (16 * XSTR * 4) + s * 32 + wcc);
      ldsm4(l0, l1, l2, l3, wlb + jp * (16 * XSTR * 4) + s * 32 + wcc);
      MMA_BF16(acc[2 * jp], xah[s], h0, h1);
      MMA_BF16(acc[2 * jp], xal[s], h0, h1);
      MMA_BF16(acc[2 * jp], xah[s], l0, l1);
      MMA_BF16(acc[2 * jp + 1], xah[s], h2, h3);
      MMA_BF16(acc[2 * jp + 1], xal[s], h2, h3);
      MMA_BF16(acc[2 * jp + 1], xah[s], l2, l3);
    }
  }

#pragma unroll
  for (int j = 0; j < 16; j++) {
    *reinterpret_cast<float2*>(&Y[(size_t)(m0 + r0) * DH + 8 * j + 2 * t]) =
        make_float2(acc[j][0], acc[j][1]);
    *reinterpret_cast<float2*>(&Y[(size_t)(m0 + r1) * DH + 8 * j + 2 * t]) =
        make_float2(acc[j][2], acc[j][3]);
  }
}

// ---------------------------------------------------------------------------
// Fused flash attention, 3x-bf16 mma, ldmatrix B-loads, P kept in registers
// (QK^T C-fragment packs directly into PV A-fragment — same-lane property).
// ---------------------------------------------------------------------------
__global__ __launch_bounds__(256, 1) void attn_kernel(
    const uint32_t* __restrict__ QpH, const uint32_t* __restrict__ QpL,
    const uint32_t* __restrict__ KpH, const uint32_t* __restrict__ KpL,
    const uint32_t* __restrict__ VpH, const uint32_t* __restrict__ VpL,
    const float* __restrict__ allele, const float* __restrict__ mask,
    float* __restrict__ Ctx) {
  extern __shared__ uint32_t usm[];
  uint32_t* KH = usm;                      // [2][64*KPS]
  uint32_t* KL = KH + 2 * 64 * KPS;
  uint32_t* VH = KL + 2 * 64 * KPS;        // [2][128*VPS]
  uint32_t* VL = VH + 2 * 128 * VPS;
  float2*   uk2 = (float2*)(VL + 2 * 128 * VPS);  // [2][64] (u, 1/u)
  float*    bks = (float*)(uk2 + 128);            // [2][64]

  const int b   = blockIdx.y;
  const int q0  = blockIdx.x * BQ;
  const int tid = threadIdx.x;
  const int w = tid >> 5, lane = tid & 31;
  const int g = lane >> 2, t = lane & 3;
  const int lm = lane >> 3, lr = lane & 7;
  const uint32_t smb = (uint32_t)__cvta_generic_to_shared(usm);
  const uint32_t kcc = ((8 * (lm >> 1) + lr) * KPS + 4 * (lm & 1)) * 4;
  const uint32_t vcc = ((8 * (lm >> 1) + lr) * VPS + 4 * (lm & 1)) * 4;
  const uint32_t VH_OFF = (4 * 64 * KPS) * 4;
  const uint32_t VL_OFF = VH_OFF + (2 * 128 * VPS) * 4;

  // ---- Q fragments direct from global (pre-scaled, packed hi/lo)
  const uint32_t* qhg = QpH + (size_t)(b * NTOK + q0 + w * 16) * 64;
  const uint32_t* qlg = QpL + (size_t)(b * NTOK + q0 + w * 16) * 64;
  uint32_t qah[8][4], qal[8][4];
#pragma unroll
  for (int s = 0; s < 8; s++) {
    qah[s][0] = qhg[g * 64 + 8 * s + t];
    qah[s][1] = qhg[(g + 8) * 64 + 8 * s + t];
    qah[s][2] = qhg[g * 64 + 8 * s + t + 4];
    qah[s][3] = qhg[(g + 8) * 64 + 8 * s + t + 4];
    qal[s][0] = qlg[g * 64 + 8 * s + t];
    qal[s][1] = qlg[(g + 8) * 64 + 8 * s + t];
    qal[s][2] = qlg[g * 64 + 8 * s + t + 4];
    qal[s][3] = qlg[(g + 8) * 64 + 8 * s + t + 4];
  }
  float aq0 = allele[b * NTOK + q0 + w * 16 + g];
  float aq1 = allele[b * NTOK + q0 + w * 16 + g + 8];
  float uq0 = __expf(0.1f * aq0), iq0 = 1.0f / uq0;
  float uq1 = __expf(0.1f * aq1), iq1 = 1.0f / uq1;

  // ---- prefetch tile 0
  {
    const uint32_t* kh = KpH + (size_t)(b * NTOK) * 64;
    const uint32_t* kl = KpL + (size_t)(b * NTOK) * 64;
#pragma unroll
    for (int it = 0; it < 4; it++) {
      int i = tid + it * 256;
      int r = i >> 4, c = i & 15;
      cp16(&KH[r * KPS + c * 4], kh + r * 64 + c * 4);
      cp16(&KL[r * KPS + c * 4], kl + r * 64 + c * 4);
    }
    const uint32_t* vh = VpH + (size_t)b * DH * (NTOK / 2);
    const uint32_t* vl = VpL + (size_t)b * DH * (NTOK / 2);
#pragma unroll
    for (int it = 0; it < 4; it++) {
      int i = tid + it * 256;
      int r = i >> 3, c = i & 7;
      cp16(&VH[r * VPS + c * 4], vh + (size_t)r * (NTOK / 2) + c * 4);
      cp16(&VL[r * VPS + c * 4], vl + (size_t)r * (NTOK / 2) + c * 4);
    }
    asm volatile("cp.async.commit_group;");
    if (tid < BK) {
      float a = allele[b * NTOK + tid];
      float u = __expf(0.1f * a);
      uk2[tid] = make_float2(u, 1.0f / u);
      bks[tid] = (1.0f - mask[b * NTOK + tid]) * -1e9f;
    }
  }

  float o[16][4];
#pragma unroll
  for (int j = 0; j < 16; j++)
#pragma unroll
    for (int q = 0; q < 4; q++) o[j][q] = 0.f;
  float m0 = -1e30f, m1 = -1e30f, l0 = 0.f, l1 = 0.f;

  for (int kt = 0; kt < NKT; kt++) {
    const int buf = kt & 1;
    asm volatile("cp.async.wait_group 0;");
    __syncthreads();

    if (kt + 1 < NKT) {
      const uint32_t* kh = KpH + (size_t)(b * NTOK + (kt + 1) * BK) * 64;
      const uint32_t* kl = KpL + (size_t)(b * NTOK + (kt + 1) * BK) * 64;
      uint32_t* dkh = KH + (buf ^ 1) * 64 * KPS;
      uint32_t* dkl = KL + (buf ^ 1) * 64 * KPS;
#pragma unroll
      for (int it = 0; it < 4; it++) {
        int i = tid + it * 256;
        int r = i >> 4, c = i & 15;
        cp16(&dkh[r * KPS + c * 4], kh + r * 64 + c * 4);
        cp16(&dkl[r * KPS + c * 4], kl + r * 64 + c * 4);
      }
      const uint32_t* vh = VpH + (size_t)b * DH * (NTOK / 2) + (kt + 1) * 32;
      const uint32_t* vl = VpL + (size_t)b * DH * (NTOK / 2) + (kt + 1) * 32;
      uint32_t* dvh = VH + (buf ^ 1) * 128 * VPS;
      uint32_t* dvl = VL + (buf ^ 1) * 128 * VPS;
#pragma unroll
      for (int it = 0; it < 4; it++) {
        int i = tid + it * 256;
        int r = i >> 3, c = i & 7;
        cp16(&dvh[r * VPS + c * 4], vh + (size_t)r * (NTOK / 2) + c * 4);
        cp16(&dvl[r * VPS + c * 4], vl + (size_t)r * (NTOK / 2) + c * 4);
      }
      asm volatile("cp.async.commit_group;");
      if (tid < BK) {
        float a = allele[b * NTOK + (kt + 1) * BK + tid];
        float u = __expf(0.1f * a);
        uk2[(buf ^ 1) * 64 + tid] = make_float2(u, 1.0f / u);
        bks[(buf ^ 1) * 64 + tid] =
            (1.0f - mask[b * NTOK + (kt + 1) * BK + tid]) * -1e9f;
      }
    }

    // ---- S = Q K^T (m16 x n64 x k128, 3-mma split, ldmatrix B)
    float sacc[8][4];
#pragma unroll
    for (int j = 0; j < 8; j++)
#pragma unroll
      for (int q = 0; q < 4; q++) sacc[j][q] = 0.f;

    const uint32_t khb = smb + (buf * 64 * KPS) * 4;
    const uint32_t klb = smb + ((2 + buf) * 64 * KPS) * 4;
#pragma unroll
    for (int s = 0; s < 8; s++) {
#pragma unroll
      for (int jp = 0; jp < 4; jp++) {
        uint32_t h0, h1, h2, h3, l0_, l1_, l2_, l3_;
        ldsm4(h0, h1, h2, h3, khb + jp * (16 * KPS * 4) + s * 32 + kcc);
        ldsm4(l0_, l1_, l2_, l3_, klb + jp * (16 * KPS * 4) + s * 32 + kcc);
        MMA_BF16(sacc[2 * jp], qah[s], h0, h1);
        MMA_BF16(sacc[2 * jp], qal[s], h0, h1);
        MMA_BF16(sacc[2 * jp], qah[s], l0_, l1_);
        MMA_BF16(sacc[2 * jp + 1], qah[s], h2, h3);
        MMA_BF16(sacc[2 * jp + 1], qal[s], h2, h3);
        MMA_BF16(sacc[2 * jp + 1], qah[s], l2_, l3_);
      }
    }

    // ---- logits = S*decay + bias; row max
    const float2* ukb = &uk2[buf * 64];
    const float*  bb  = &bks[buf * 64];
    float rmax0 = -1e30f, rmax1 = -1e30f;
#pragma unroll
    for (int j = 0; j < 8; j++) {
      int c = 8 * j + 2 * t;
      float4 uu = *reinterpret_cast<const float4*>(&ukb[c]);
      float2 bias = *reinterpret_cast<const float2*>(&bb[c]);
      float d00 = fminf(uq0 * uu.y, iq0 * uu.x);
      float d01 = fminf(uq0 * uu.w, iq0 * uu.z);
      float d10 = fminf(uq1 * uu.y, iq1 * uu.x);
      float d11 = fminf(uq1 * uu.w, iq1 * uu.z);
      sacc[j][0] = sacc[j][0] * d00 + bias.x;
      sacc[j][1] = sacc[j][1] * d01 + bias.y;
      sacc[j][2] = sacc[j][2] * d10 + bias.x;
      sacc[j][3] = sacc[j][3] * d11 + bias.y;
      rmax0 = fmaxf(rmax0, fmaxf(sacc[j][0], sacc[j][1]));
      rmax1 = fmaxf(rmax1, fmaxf(sacc[j][2], sacc[j][3]));
    }
    rmax0 = fmaxf(rmax0, __shfl_xor_sync(0xffffffffu, rmax0, 1));
    rmax0 = fmaxf(rmax0, __shfl_xor_sync(0xffffffffu, rmax0, 2));
    rmax1 = fmaxf(rmax1, __shfl_xor_sync(0xffffffffu, rmax1, 1));
    rmax1 = fmaxf(rmax1, __shfl_xor_sync(0xffffffffu, rmax1, 2));

    float mn0 = fmaxf(m0, rmax0), mn1 = fmaxf(m1, rmax1);
    float sum0 = 0.f, sum1 = 0.f;
#pragma unroll
    for (int j = 0; j < 8; j++) {
      float p00 = __expf(sacc[j][0] - mn0);
      float p01 = __expf(sacc[j][1] - mn0);
      float p10 = __expf(sacc[j][2] - mn1);
      float p11 = __expf(sacc[j][3] - mn1);
      sum0 += p00 + p01;
      sum1 += p10 + p11;
      sacc[j][0] = p00; sacc[j][1] = p01;
      sacc[j][2] = p10; sacc[j][3] = p11;
    }
    sum0 += __shfl_xor_sync(0xffffffffu, sum0, 1);
    sum0 += __shfl_xor_sync(0xffffffffu, sum0, 2);
    sum1 += __shfl_xor_sync(0xffffffffu, sum1, 1);
    sum1 += __shfl_xor_sync(0xffffffffu, sum1, 2);

    float cs0 = __expf(m0 - mn0), cs1 = __expf(m1 - mn1);
    l0 = l0 * cs0 + sum0;
    l1 = l1 * cs1 + sum1;
    m0 = mn0; m1 = mn1;
#pragma unroll
    for (int j = 0; j < 16; j++) {
      o[j][0] *= cs0; o[j][1] *= cs0;
      o[j][2] *= cs1; o[j][3] *= cs1;
    }

    // ---- O += P V (m16 x n128 x k64): C-fragment packs directly into A
    const uint32_t vhb = smb + VH_OFF + (buf * 128 * VPS) * 4;
    const uint32_t vlb = smb + VL_OFF + (buf * 128 * VPS) * 4;
#pragma unroll
    for (int s2 = 0; s2 < 4; s2++) {
      uint32_t pah[4], pal[4];
      pah[0] = bfpack(sacc[2 * s2][0], sacc[2 * s2][1]);
      pah[1] = bfpack(sacc[2 * s2][2], sacc[2 * s2][3]);
      pah[2] = bfpack(sacc[2 * s2 + 1][0], sacc[2 * s2 + 1][1]);
      pah[3] = bfpack(sacc[2 * s2 + 1][2], sacc[2 * s2 + 1][3]);
      pal[0] = bfres(pah[0], sacc[2 * s2][0], sacc[2 * s2][1]);
      pal[1] = bfres(pah[1], sacc[2 * s2][2], sacc[2 * s2][3]);
      pal[2] = bfres(pah[2], sacc[2 * s2 + 1][0], sacc[2 * s2 + 1][1]);
      pal[3] = bfres(pah[3], sacc[2 * s2 + 1][2], sacc[2 * s2 + 1][3]);
#pragma unroll
      for (int jp2 = 0; jp2 < 8; jp2++) {
        uint32_t h0, h1, h2, h3, l0_, l1_, l2_, l3_;
        ldsm4(h0, h1, h2, h3, vhb + jp2 * (16 * VPS * 4) + s2 * 32 + vcc);
        ldsm4(l0_, l1_, l2_, l3_, vlb + jp2 * (16 * VPS * 4) + s2 * 32 + vcc);
        MMA_BF16(o[2 * jp2], pah, h0, h1);
        MMA_BF16(o[2 * jp2], pal, h0, h1);
        MMA_BF16(o[2 * jp2], pah, l0_, l1_);
        MMA_BF16(o[2 * jp2 + 1], pah, h2, h3);
        MMA_BF16(o[2 * jp2 + 1], pal, h2, h3);
        MMA_BF16(o[2 * jp2 + 1], pah, l2_, l3_);
      }
    }
  }

  // ---- epilogue
  float inv0 = 1.0f / l0, inv1 = 1.0f / l1;
  float* Og = Ctx + (size_t)(b * NTOK + q0) * DH;
#pragma unroll
  for (int j2 = 0; j2 < 16; j2++) {
    *reinterpret_cast<float2*>(&Og[(w * 16 + g) * DH + 8 * j2 + 2 * t]) =
        make_float2(o[j2][0] * inv0, o[j2][1] * inv0);
    *reinterpret_cast<float2*>(&Og[(w * 16 + g + 8) * DH + 8 * j2 + 2 * t]) =
        make_float2(o[j2][2] * inv1, o[j2][3] * inv1);
  }
}

// ---------------------------------------------------------------------------
extern "C" void kernel_launch(void* const* d_in, const int* in_sizes, int n_in,
                              void* d_out, int out_size) {
  const float* X  = (const float*)d_in[0];
  const float* al = (const float*)d_in[1];
  const float* mk = (const float*)d_in[2];
  const float* Wq = (const float*)d_in[3];
  const float* Wk = (const float*)d_in[4];
  const float* Wv = (const float*)d_in[5];
  const float* Wo = (const float*)d_in[6];
  float* out = (float*)d_out;

  uint32_t *qh, *ql, *kh, *kl, *vh, *vl;
  float* dc;
  cudaGetSymbolAddress((void**)&qh, g_qh);
  cudaGetSymbolAddress((void**)&ql, g_ql);
  cudaGetSymbolAddress((void**)&kh, g_kh);
  cudaGetSymbolAddress((void**)&kl, g_kl);
  cudaGetSymbolAddress((void**)&vh, g_vh);
  cudaGetSymbolAddress((void**)&vl, g_vl);
  cudaGetSymbolAddress((void**)&dc, g_c);

  cudaFuncSetAttribute(qkv_kernel,
                       cudaFuncAttributeMaxDynamicSharedMemorySize, QKV_SMEM);
  cudaFuncSetAttribute(oproj_kernel,
                       cudaFuncAttributeMaxDynamicSharedMemorySize, QKV_SMEM);
  cudaFuncSetAttribute(attn_kernel,
                       cudaFuncAttributeMaxDynamicSharedMemorySize, ATTN_SMEM);

  qkv_kernel<<<NB * NTOK / 128, 256, QKV_SMEM>>>(X, Wq, Wk, Wv, qh, ql, kh, kl,
                                                 vh, vl);
  attn_kernel<<<dim3(NTOK / BQ, NB), 256, ATTN_SMEM>>>(qh, ql, kh, kl, vh, vl,
                                                       al, mk, dc);
  oproj_kernel<<<NB * NTOK / 128, 256, QKV_SMEM>>>(dc, Wo, out);
}